// round 11
// baseline (speedup 1.0000x reference)
#include <cuda_runtime.h>
#include <cuda_fp16.h>
#include <cstdint>

// ---------------------------------------------------------------------------
// GraphConvolution: out = SpMM(COO adj, x @ W) + bias
// Round 10: R8 topology (prep overlapped with GEMM). Gather rewritten to
// decouple index stream from data stream: 8 edge headers loaded cooperatively
// per warp (shuffle-broadcast), then 8 independent support loads (MLP=8).
// ---------------------------------------------------------------------------

#define D 512
#define MAX_NODES 50000
#define MAX_EDGES 400000

__device__ __half g_support[(size_t)MAX_NODES * D];   // 51.2 MB
__device__ int    g_counts[MAX_NODES];
__device__ int    g_offsets[MAX_NODES + 1];
__device__ int    g_cursors[MAX_NODES];
__device__ int    g_blocksums[256];
__device__ int2   g_perm[MAX_EDGES];

// Host-side fork/join resources, created once at load (not during capture).
struct ForkJoin {
    cudaStream_t side;
    cudaEvent_t  fork_ev, join_ev;
    ForkJoin() {
        cudaStreamCreateWithFlags(&side, cudaStreamNonBlocking);
        cudaEventCreateWithFlags(&fork_ev, cudaEventDisableTiming);
        cudaEventCreateWithFlags(&join_ev, cudaEventDisableTiming);
    }
};
static ForkJoin g_fj;

// ========================= Prep kernels ====================================
__global__ void zero_counts_kernel(int n) {
    int i = blockIdx.x * blockDim.x + threadIdx.x;
    if (i < n) g_counts[i] = 0;
}

__global__ void hist_kernel(const int* __restrict__ rows, int E) {
    int e = blockIdx.x * blockDim.x + threadIdx.x;
    if (e < E) atomicAdd(&g_counts[rows[e]], 1);
}

__global__ __launch_bounds__(512)
void scan1_kernel(int n) {
    __shared__ int ws[16];
    const int tid  = threadIdx.x;
    const int lane = tid & 31;
    const int wid  = tid >> 5;
    const int i = blockIdx.x * 512 + tid;
    const int v = (i < n) ? g_counts[i] : 0;

    int x = v;
    #pragma unroll
    for (int d = 1; d < 32; d <<= 1) {
        int y = __shfl_up_sync(0xffffffffu, x, d);
        if (lane >= d) x += y;
    }
    if (lane == 31) ws[wid] = x;
    __syncthreads();
    if (wid == 0) {
        int w = (lane < 16) ? ws[lane] : 0;
        #pragma unroll
        for (int d = 1; d < 16; d <<= 1) {
            int y = __shfl_up_sync(0xffffffffu, w, d);
            if (lane >= d) w += y;
        }
        if (lane < 16) ws[lane] = w;
    }
    __syncthreads();
    const int excl = (wid ? ws[wid - 1] : 0) + x - v;
    if (i < n) g_offsets[i] = excl;
    if (tid == 511) g_blocksums[blockIdx.x] = ws[15];
}

__global__ __launch_bounds__(128)
void scan2_kernel(int nb) {
    __shared__ int ws[4];
    const int tid  = threadIdx.x;
    const int lane = tid & 31;
    const int wid  = tid >> 5;
    const int v = (tid < nb) ? g_blocksums[tid] : 0;
    int x = v;
    #pragma unroll
    for (int d = 1; d < 32; d <<= 1) {
        int y = __shfl_up_sync(0xffffffffu, x, d);
        if (lane >= d) x += y;
    }
    if (lane == 31) ws[wid] = x;
    __syncthreads();
    if (wid == 0 && lane < 4) {
        int w = ws[lane];
        #pragma unroll
        for (int d = 1; d < 4; d <<= 1) {
            int y = __shfl_up_sync(0x0000000fu, w, d);
            if (lane >= d) w += y;
        }
        ws[lane] = w;
    }
    __syncthreads();
    const int excl = (wid ? ws[wid - 1] : 0) + x - v;
    if (tid < nb) g_blocksums[tid] = excl;
}

__global__ __launch_bounds__(512)
void scan3_kernel(int n, int E) {
    const int i = blockIdx.x * 512 + threadIdx.x;
    if (i < n) {
        const int off = g_offsets[i] + g_blocksums[blockIdx.x];
        g_offsets[i] = off;
        g_cursors[i] = off;
    }
    if (i == 0) g_offsets[n] = E;
}

__global__ void place_kernel(const int* __restrict__ rows,
                             const int* __restrict__ cols,
                             const float* __restrict__ vals,
                             int E) {
    int e = blockIdx.x * blockDim.x + threadIdx.x;
    if (e >= E) return;
    int pos = atomicAdd(&g_cursors[rows[e]], 1);
    g_perm[pos] = make_int2(cols[e], __float_as_int(vals[e]));
}

// ---------------------------------------------------------------------------
// FP16 tensor-core GEMM (fp32 accum) -> fp16 output.  (R7/R8, proven)
// CTA tile 128x128x32, 8 warps (4x2), warp tile 32x64, mma.m16n8k16.f16.
// ---------------------------------------------------------------------------
#define BM 128
#define BN 128
#define BK 32
#define KP (BK / 2)
#define SSTRIDE (BM + 8)

__device__ __forceinline__ uint32_t pack_h2(float a, float b) {
    __half2 h = __floats2half2_rn(a, b);
    return *reinterpret_cast<uint32_t*>(&h);
}

__global__ __launch_bounds__(256, 2)
void f16_gemm_kernel(const float* __restrict__ A,
                     const float* __restrict__ B,
                     __half* __restrict__ C,
                     int M) {
    constexpr int N = 512, K = 512;

    __shared__ uint32_t As[KP][SSTRIDE];
    __shared__ uint32_t Bs[KP][SSTRIDE];

    const int tid  = threadIdx.x;
    const int wid  = tid >> 5;
    const int lane = tid & 31;
    const int g    = lane >> 2;
    const int tg   = lane & 3;

    const int wm = (wid >> 1) * 32;
    const int wn = (wid & 1) * 64;

    const int m_base = blockIdx.y * BM;
    const int n_base = blockIdx.x * BN;

    float acc[2][8][4];
    #pragma unroll
    for (int mi = 0; mi < 2; mi++)
        #pragma unroll
        for (int ni = 0; ni < 8; ni++)
            #pragma unroll
            for (int r = 0; r < 4; r++) acc[mi][ni][r] = 0.0f;

    float4 a_stage[4];
    float4 b_stage[2][2];

    auto load_tile = [&](int k0) {
        #pragma unroll
        for (int j = 0; j < 4; j++) {
            const int f   = tid * 4 + j;
            const int row = f >> 3;
            const int kq  = (f & 7) * 4;
            a_stage[j] = make_float4(0.f, 0.f, 0.f, 0.f);
            if (m_base + row < M)
                a_stage[j] = *reinterpret_cast<const float4*>(
                                 A + (size_t)(m_base + row) * K + k0 + kq);
        }
        #pragma unroll
        for (int j = 0; j < 2; j++) {
            const int p  = tid * 2 + j;
            const int kp = p >> 5;
            const int nq = (p & 31) * 4;
            b_stage[j][0] = *reinterpret_cast<const float4*>(
                                B + (size_t)(k0 + 2 * kp) * N + n_base + nq);
            b_stage[j][1] = *reinterpret_cast<const float4*>(
                                B + (size_t)(k0 + 2 * kp + 1) * N + n_base + nq);
        }
    };

    auto commit_tile = [&]() {
        #pragma unroll
        for (int j = 0; j < 4; j++) {
            const int f   = tid * 4 + j;
            const int row = f >> 3;
            const int kq  = (f & 7) * 4;
            const int kp  = kq >> 1;
            As[kp    ][row] = pack_h2(a_stage[j].x, a_stage[j].y);
            As[kp + 1][row] = pack_h2(a_stage[j].z, a_stage[j].w);
        }
        #pragma unroll
        for (int j = 0; j < 2; j++) {
            const int p  = tid * 2 + j;
            const int kp = p >> 5;
            const int nq = (p & 31) * 4;
            uint4 t;
            t.x = pack_h2(b_stage[j][0].x, b_stage[j][1].x);
            t.y = pack_h2(b_stage[j][0].y, b_stage[j][1].y);
            t.z = pack_h2(b_stage[j][0].z, b_stage[j][1].z);
            t.w = pack_h2(b_stage[j][0].w, b_stage[j][1].w);
            *reinterpret_cast<uint4*>(&Bs[kp][nq]) = t;
        }
    };

    load_tile(0);

    for (int k0 = 0; k0 < K; k0 += BK) {
        commit_tile();
        __syncthreads();

        if (k0 + BK < K) load_tile(k0 + BK);

        #pragma unroll
        for (int ks = 0; ks < KP; ks += 8) {
            uint32_t a[2][4], b[8][2];
            #pragma unroll
            for (int mi = 0; mi < 2; mi++) {
                const int m0 = wm + mi * 16;
                a[mi][0] = As[ks + tg    ][m0 + g    ];
                a[mi][1] = As[ks + tg    ][m0 + g + 8];
                a[mi][2] = As[ks + tg + 4][m0 + g    ];
                a[mi][3] = As[ks + tg + 4][m0 + g + 8];
            }
            #pragma unroll
            for (int ni = 0; ni < 8; ni++) {
                const int n0 = wn + ni * 8;
                b[ni][0] = Bs[ks + tg    ][n0 + g];
                b[ni][1] = Bs[ks + tg + 4][n0 + g];
            }
            #pragma unroll
            for (int mi = 0; mi < 2; mi++)
                #pragma unroll
                for (int ni = 0; ni < 8; ni++) {
                    asm volatile(
                        "mma.sync.aligned.m16n8k16.row.col.f32.f16.f16.f32 "
                        "{%0,%1,%2,%3}, {%4,%5,%6,%7}, {%8,%9}, {%0,%1,%2,%3};"
                        : "+f"(acc[mi][ni][0]), "+f"(acc[mi][ni][1]),
                          "+f"(acc[mi][ni][2]), "+f"(acc[mi][ni][3])
                        : "r"(a[mi][0]), "r"(a[mi][1]), "r"(a[mi][2]), "r"(a[mi][3]),
                          "r"(b[ni][0]), "r"(b[ni][1]));
                }
        }
        __syncthreads();
    }

    #pragma unroll
    for (int mi = 0; mi < 2; mi++) {
        const int row0 = m_base + wm + mi * 16 + g;
        const int row1 = row0 + 8;
        #pragma unroll
        for (int ni = 0; ni < 8; ni++) {
            const int col = n_base + wn + ni * 8 + 2 * tg;
            if (row0 < M) {
                __half2 h = __floats2half2_rn(acc[mi][ni][0], acc[mi][ni][1]);
                *reinterpret_cast<__half2*>(C + (size_t)row0 * N + col) = h;
            }
            if (row1 < M) {
                __half2 h = __floats2half2_rn(acc[mi][ni][2], acc[mi][ni][3]);
                *reinterpret_cast<__half2*>(C + (size_t)row1 * N + col) = h;
            }
        }
    }
}

// ---------------------------------------------------------------------------
// Row-gather: 4 warps per output row. Index/data decoupled: 8 edge headers
// loaded cooperatively (lanes 0..7) and shuffle-broadcast, then 8 independent
// support loads issued back-to-back (MLP=8), then FMAs.
// ---------------------------------------------------------------------------
__global__ __launch_bounds__(256)
void row_gather_kernel(const float* __restrict__ bias,
                       float* __restrict__ out,
                       int n_rows) {
    const int gw   = (blockIdx.x * blockDim.x + threadIdx.x) >> 5;
    const int lane = threadIdx.x & 31;
    const int row  = gw >> 2;
    const int part = gw & 3;
    if (row >= n_rows) return;

    const int s   = g_offsets[row];
    const int deg = g_offsets[row + 1] - s;
    const int fo  = part * 32 + lane;   // uint2 index within row (4 halves)

    float4 acc = make_float4(0.f, 0.f, 0.f, 0.f);

    for (int base = 0; base < deg; base += 8) {
        // cooperative header load: lanes 0..7 each fetch one edge
        int2 myp = make_int2(0, 0);
        if (lane < 8 && base + lane < deg)
            myp = __ldcs(&g_perm[s + base + lane]);

        // broadcast headers to the whole warp
        int   cols[8];
        float vals[8];
        #pragma unroll
        for (int j = 0; j < 8; j++) {
            cols[j] = __shfl_sync(0xffffffffu, myp.x, j);
            vals[j] = __int_as_float(__shfl_sync(0xffffffffu, myp.y, j));
        }

        // issue all support loads (independent; MLP = 8)
        uint2 m[8];
        #pragma unroll
        for (int j = 0; j < 8; j++) {
            if (base + j < deg)
                m[j] = __ldg(reinterpret_cast<const uint2*>(
                           g_support + (size_t)cols[j] * D) + fo);
        }

        // accumulate
        #pragma unroll
        for (int j = 0; j < 8; j++) {
            if (base + j < deg) {
                const float2 a = __half22float2(
                    *reinterpret_cast<const __half2*>(&m[j].x));
                const float2 b = __half22float2(
                    *reinterpret_cast<const __half2*>(&m[j].y));
                acc.x += vals[j] * a.x;
                acc.y += vals[j] * a.y;
                acc.z += vals[j] * b.x;
                acc.w += vals[j] * b.y;
            }
        }
    }

    const float4 b = __ldg(reinterpret_cast<const float4*>(bias) + fo);
    const float4 r = make_float4(acc.x + b.x, acc.y + b.y,
                                 acc.z + b.z, acc.w + b.w);
    __stcs(reinterpret_cast<float4*>(out + (size_t)row * D) + fo, r);
}

// ========================= Launch ==========================================
extern "C" void kernel_launch(void* const* d_in, const int* in_sizes, int n_in,
                              void* d_out, int out_size) {
    const float* x        = (const float*)d_in[0];
    const int*   adj_rows = (const int*)  d_in[1];
    const int*   adj_cols = (const int*)  d_in[2];
    const float* adj_vals = (const float*)d_in[3];
    const float* weight   = (const float*)d_in[4];
    const float* bias     = (const float*)d_in[5];
    float* out = (float*)d_out;

    const int M = in_sizes[0] / D;   // N_NODES
    const int E = in_sizes[1];       // N_EDGES

    // ---- fork: prep chain on side stream, GEMM on main stream ----
    cudaEventRecord(g_fj.fork_ev, 0);
    cudaStreamWaitEvent(g_fj.side, g_fj.fork_ev, 0);

    zero_counts_kernel<<<(M + 255) / 256, 256, 0, g_fj.side>>>(M);
    hist_kernel<<<(E + 255) / 256, 256, 0, g_fj.side>>>(adj_rows, E);
    const int nb = (M + 511) / 512;
    scan1_kernel<<<nb, 512, 0, g_fj.side>>>(M);
    scan2_kernel<<<1, 128, 0, g_fj.side>>>(nb);
    scan3_kernel<<<nb, 512, 0, g_fj.side>>>(M, E);
    place_kernel<<<(E + 255) / 256, 256, 0, g_fj.side>>>(adj_rows, adj_cols,
                                                         adj_vals, E);
    cudaEventRecord(g_fj.join_ev, g_fj.side);

    // GEMM on the main (capture) stream, concurrent with prep
    {
        __half* support;
        cudaGetSymbolAddress((void**)&support, g_support);
        dim3 grid(D / BN, (M + BM - 1) / BM);
        f16_gemm_kernel<<<grid, 256>>>(x, weight, support, M);
    }

    // ---- join: gather needs both GEMM output and CSR ----
    cudaStreamWaitEvent(0, g_fj.join_ev, 0);
    {
        int total_warps = 4 * M;
        int blocks = (total_warps + 7) / 8;
        row_gather_kernel<<<blocks, 256>>>(bias, out, M);
    }
}

// round 12
// speedup vs baseline: 1.1564x; 1.1564x over previous
#include <cuda_runtime.h>
#include <cuda_fp16.h>
#include <cstdint>

// ---------------------------------------------------------------------------
// GraphConvolution: out = SpMM(COO adj, x @ W) + bias
// Round 11: gather reverted to R8 (proven). GEMM gets double-buffered smem:
// one __syncthreads per K-tile (was 2), commit overlaps other warps' compute.
// Prep overlapped with GEMM on side stream (R8 topology, proven).
// ---------------------------------------------------------------------------

#define D 512
#define MAX_NODES 50000
#define MAX_EDGES 400000

__device__ __half g_support[(size_t)MAX_NODES * D];   // 51.2 MB
__device__ int    g_counts[MAX_NODES];
__device__ int    g_offsets[MAX_NODES + 1];
__device__ int    g_cursors[MAX_NODES];
__device__ int    g_blocksums[256];
__device__ int2   g_perm[MAX_EDGES];

// Host-side fork/join resources, created once at load (not during capture).
struct ForkJoin {
    cudaStream_t side;
    cudaEvent_t  fork_ev, join_ev;
    ForkJoin() {
        cudaStreamCreateWithFlags(&side, cudaStreamNonBlocking);
        cudaEventCreateWithFlags(&fork_ev, cudaEventDisableTiming);
        cudaEventCreateWithFlags(&join_ev, cudaEventDisableTiming);
    }
};
static ForkJoin g_fj;

// ========================= Prep kernels ====================================
__global__ void zero_counts_kernel(int n) {
    int i = blockIdx.x * blockDim.x + threadIdx.x;
    if (i < n) g_counts[i] = 0;
}

__global__ void hist_kernel(const int* __restrict__ rows, int E) {
    int e = blockIdx.x * blockDim.x + threadIdx.x;
    if (e < E) atomicAdd(&g_counts[rows[e]], 1);
}

__global__ __launch_bounds__(512)
void scan1_kernel(int n) {
    __shared__ int ws[16];
    const int tid  = threadIdx.x;
    const int lane = tid & 31;
    const int wid  = tid >> 5;
    const int i = blockIdx.x * 512 + tid;
    const int v = (i < n) ? g_counts[i] : 0;

    int x = v;
    #pragma unroll
    for (int d = 1; d < 32; d <<= 1) {
        int y = __shfl_up_sync(0xffffffffu, x, d);
        if (lane >= d) x += y;
    }
    if (lane == 31) ws[wid] = x;
    __syncthreads();
    if (wid == 0) {
        int w = (lane < 16) ? ws[lane] : 0;
        #pragma unroll
        for (int d = 1; d < 16; d <<= 1) {
            int y = __shfl_up_sync(0xffffffffu, w, d);
            if (lane >= d) w += y;
        }
        if (lane < 16) ws[lane] = w;
    }
    __syncthreads();
    const int excl = (wid ? ws[wid - 1] : 0) + x - v;
    if (i < n) g_offsets[i] = excl;
    if (tid == 511) g_blocksums[blockIdx.x] = ws[15];
}

__global__ __launch_bounds__(128)
void scan2_kernel(int nb) {
    __shared__ int ws[4];
    const int tid  = threadIdx.x;
    const int lane = tid & 31;
    const int wid  = tid >> 5;
    const int v = (tid < nb) ? g_blocksums[tid] : 0;
    int x = v;
    #pragma unroll
    for (int d = 1; d < 32; d <<= 1) {
        int y = __shfl_up_sync(0xffffffffu, x, d);
        if (lane >= d) x += y;
    }
    if (lane == 31) ws[wid] = x;
    __syncthreads();
    if (wid == 0 && lane < 4) {
        int w = ws[lane];
        #pragma unroll
        for (int d = 1; d < 4; d <<= 1) {
            int y = __shfl_up_sync(0x0000000fu, w, d);
            if (lane >= d) w += y;
        }
        ws[lane] = w;
    }
    __syncthreads();
    const int excl = (wid ? ws[wid - 1] : 0) + x - v;
    if (tid < nb) g_blocksums[tid] = excl;
}

__global__ __launch_bounds__(512)
void scan3_kernel(int n, int E) {
    const int i = blockIdx.x * 512 + threadIdx.x;
    if (i < n) {
        const int off = g_offsets[i] + g_blocksums[blockIdx.x];
        g_offsets[i] = off;
        g_cursors[i] = off;
    }
    if (i == 0) g_offsets[n] = E;
}

__global__ void place_kernel(const int* __restrict__ rows,
                             const int* __restrict__ cols,
                             const float* __restrict__ vals,
                             int E) {
    int e = blockIdx.x * blockDim.x + threadIdx.x;
    if (e >= E) return;
    int pos = atomicAdd(&g_cursors[rows[e]], 1);
    g_perm[pos] = make_int2(cols[e], __float_as_int(vals[e]));
}

// ---------------------------------------------------------------------------
// FP16 tensor-core GEMM (fp32 accum), double-buffered smem, fp16 output.
// CTA tile 128x128x32, 8 warps (4x2), warp tile 32x64, mma.m16n8k16.f16.
// One __syncthreads per K-tile; commit of tile c+1 overlaps compute of c.
// ---------------------------------------------------------------------------
#define BM 128
#define BN 128
#define BK 32
#define KP (BK / 2)
#define SSTRIDE (BM + 8)
#define NTILES (512 / BK)   // 16

__device__ __forceinline__ uint32_t pack_h2(float a, float b) {
    __half2 h = __floats2half2_rn(a, b);
    return *reinterpret_cast<uint32_t*>(&h);
}

__global__ __launch_bounds__(256, 2)
void f16_gemm_kernel(const float* __restrict__ A,
                     const float* __restrict__ B,
                     __half* __restrict__ C,
                     int M) {
    constexpr int N = 512, K = 512;

    __shared__ uint32_t As[2][KP][SSTRIDE];   // 17.4 KB
    __shared__ uint32_t Bs[2][KP][SSTRIDE];   // 17.4 KB

    const int tid  = threadIdx.x;
    const int wid  = tid >> 5;
    const int lane = tid & 31;
    const int g    = lane >> 2;
    const int tg   = lane & 3;

    const int wm = (wid >> 1) * 32;
    const int wn = (wid & 1) * 64;

    const int m_base = blockIdx.y * BM;
    const int n_base = blockIdx.x * BN;

    float acc[2][8][4];
    #pragma unroll
    for (int mi = 0; mi < 2; mi++)
        #pragma unroll
        for (int ni = 0; ni < 8; ni++)
            #pragma unroll
            for (int r = 0; r < 4; r++) acc[mi][ni][r] = 0.0f;

    float4 a_stage[4];
    float4 b_stage[2][2];

    auto load_tile = [&](int k0) {
        #pragma unroll
        for (int j = 0; j < 4; j++) {
            const int f   = tid * 4 + j;
            const int row = f >> 3;
            const int kq  = (f & 7) * 4;
            a_stage[j] = make_float4(0.f, 0.f, 0.f, 0.f);
            if (m_base + row < M)
                a_stage[j] = *reinterpret_cast<const float4*>(
                                 A + (size_t)(m_base + row) * K + k0 + kq);
        }
        #pragma unroll
        for (int j = 0; j < 2; j++) {
            const int p  = tid * 2 + j;
            const int kp = p >> 5;
            const int nq = (p & 31) * 4;
            b_stage[j][0] = *reinterpret_cast<const float4*>(
                                B + (size_t)(k0 + 2 * kp) * N + n_base + nq);
            b_stage[j][1] = *reinterpret_cast<const float4*>(
                                B + (size_t)(k0 + 2 * kp + 1) * N + n_base + nq);
        }
    };

    auto commit_tile = [&](int buf) {
        #pragma unroll
        for (int j = 0; j < 4; j++) {
            const int f   = tid * 4 + j;
            const int row = f >> 3;
            const int kq  = (f & 7) * 4;
            const int kp  = kq >> 1;
            As[buf][kp    ][row] = pack_h2(a_stage[j].x, a_stage[j].y);
            As[buf][kp + 1][row] = pack_h2(a_stage[j].z, a_stage[j].w);
        }
        #pragma unroll
        for (int j = 0; j < 2; j++) {
            const int p  = tid * 2 + j;
            const int kp = p >> 5;
            const int nq = (p & 31) * 4;
            uint4 t;
            t.x = pack_h2(b_stage[j][0].x, b_stage[j][1].x);
            t.y = pack_h2(b_stage[j][0].y, b_stage[j][1].y);
            t.z = pack_h2(b_stage[j][0].z, b_stage[j][1].z);
            t.w = pack_h2(b_stage[j][0].w, b_stage[j][1].w);
            *reinterpret_cast<uint4*>(&Bs[buf][kp][nq]) = t;
        }
    };

    // prologue: tile 0 -> buffer 0
    load_tile(0);
    commit_tile(0);

    for (int c = 0; c < NTILES; c++) {
        const int buf = c & 1;
        __syncthreads();   // tile c committed; prior compute on buf^1 done

        if (c + 1 < NTILES) load_tile((c + 1) * BK);

        // compute on buffer buf
        #pragma unroll
        for (int ks = 0; ks < KP; ks += 8) {
            uint32_t a[2][4], b[8][2];
            #pragma unroll
            for (int mi = 0; mi < 2; mi++) {
                const int m0 = wm + mi * 16;
                a[mi][0] = As[buf][ks + tg    ][m0 + g    ];
                a[mi][1] = As[buf][ks + tg    ][m0 + g + 8];
                a[mi][2] = As[buf][ks + tg + 4][m0 + g    ];
                a[mi][3] = As[buf][ks + tg + 4][m0 + g + 8];
            }
            #pragma unroll
            for (int ni = 0; ni < 8; ni++) {
                const int n0 = wn + ni * 8;
                b[ni][0] = Bs[buf][ks + tg    ][n0 + g];
                b[ni][1] = Bs[buf][ks + tg + 4][n0 + g];
            }
            #pragma unroll
            for (int mi = 0; mi < 2; mi++)
                #pragma unroll
                for (int ni = 0; ni < 8; ni++) {
                    asm volatile(
                        "mma.sync.aligned.m16n8k16.row.col.f32.f16.f16.f32 "
                        "{%0,%1,%2,%3}, {%4,%5,%6,%7}, {%8,%9}, {%0,%1,%2,%3};"
                        : "+f"(acc[mi][ni][0]), "+f"(acc[mi][ni][1]),
                          "+f"(acc[mi][ni][2]), "+f"(acc[mi][ni][3])
                        : "r"(a[mi][0]), "r"(a[mi][1]), "r"(a[mi][2]), "r"(a[mi][3]),
                          "r"(b[ni][0]), "r"(b[ni][1]));
                }
        }

        // commit tile c+1 into the other buffer (no sync needed: prior
        // compute on buf^1 finished before this iteration's top sync)
        if (c + 1 < NTILES) commit_tile(buf ^ 1);
    }

    #pragma unroll
    for (int mi = 0; mi < 2; mi++) {
        const int row0 = m_base + wm + mi * 16 + g;
        const int row1 = row0 + 8;
        #pragma unroll
        for (int ni = 0; ni < 8; ni++) {
            const int col = n_base + wn + ni * 8 + 2 * tg;
            if (row0 < M) {
                __half2 h = __floats2half2_rn(acc[mi][ni][0], acc[mi][ni][1]);
                *reinterpret_cast<__half2*>(C + (size_t)row0 * N + col) = h;
            }
            if (row1 < M) {
                __half2 h = __floats2half2_rn(acc[mi][ni][2], acc[mi][ni][3]);
                *reinterpret_cast<__half2*>(C + (size_t)row1 * N + col) = h;
            }
        }
    }
}

// ---------------------------------------------------------------------------
// Row-gather (fp16 support): 4 warps per output row, 4-edge unroll. (R8 exact)
// ---------------------------------------------------------------------------
__global__ __launch_bounds__(256)
void row_gather_kernel(const float* __restrict__ bias,
                       float* __restrict__ out,
                       int n_rows) {
    const int gw   = (blockIdx.x * blockDim.x + threadIdx.x) >> 5;
    const int lane = threadIdx.x & 31;
    const int row  = gw >> 2;
    const int part = gw & 3;
    if (row >= n_rows) return;

    const int s = g_offsets[row];
    const int e = g_offsets[row + 1];
    const int fo = part * 32 + lane;

    float4 acc = make_float4(0.f, 0.f, 0.f, 0.f);

    int i = s;
    for (; i + 3 < e; i += 4) {
        const int2 cv0 = __ldcs(&g_perm[i]);
        const int2 cv1 = __ldcs(&g_perm[i + 1]);
        const int2 cv2 = __ldcs(&g_perm[i + 2]);
        const int2 cv3 = __ldcs(&g_perm[i + 3]);
        const uint2 m0 = __ldg(reinterpret_cast<const uint2*>(
                             g_support + (size_t)cv0.x * D) + fo);
        const uint2 m1 = __ldg(reinterpret_cast<const uint2*>(
                             g_support + (size_t)cv1.x * D) + fo);
        const uint2 m2 = __ldg(reinterpret_cast<const uint2*>(
                             g_support + (size_t)cv2.x * D) + fo);
        const uint2 m3 = __ldg(reinterpret_cast<const uint2*>(
                             g_support + (size_t)cv3.x * D) + fo);
        const float v0 = __int_as_float(cv0.y);
        const float v1 = __int_as_float(cv1.y);
        const float v2 = __int_as_float(cv2.y);
        const float v3 = __int_as_float(cv3.y);

        float2 a0 = __half22float2(*reinterpret_cast<const __half2*>(&m0.x));
        float2 b0 = __half22float2(*reinterpret_cast<const __half2*>(&m0.y));
        float2 a1 = __half22float2(*reinterpret_cast<const __half2*>(&m1.x));
        float2 b1 = __half22float2(*reinterpret_cast<const __half2*>(&m1.y));
        float2 a2 = __half22float2(*reinterpret_cast<const __half2*>(&m2.x));
        float2 b2 = __half22float2(*reinterpret_cast<const __half2*>(&m2.y));
        float2 a3 = __half22float2(*reinterpret_cast<const __half2*>(&m3.x));
        float2 b3 = __half22float2(*reinterpret_cast<const __half2*>(&m3.y));

        acc.x += v0 * a0.x + v1 * a1.x + v2 * a2.x + v3 * a3.x;
        acc.y += v0 * a0.y + v1 * a1.y + v2 * a2.y + v3 * a3.y;
        acc.z += v0 * b0.x + v1 * b1.x + v2 * b2.x + v3 * b3.x;
        acc.w += v0 * b0.y + v1 * b1.y + v2 * b2.y + v3 * b3.y;
    }
    for (; i < e; i++) {
        const int2 cv = __ldcs(&g_perm[i]);
        const float v = __int_as_float(cv.y);
        const uint2 m = __ldg(reinterpret_cast<const uint2*>(
                            g_support + (size_t)cv.x * D) + fo);
        float2 a = __half22float2(*reinterpret_cast<const __half2*>(&m.x));
        float2 b = __half22float2(*reinterpret_cast<const __half2*>(&m.y));
        acc.x += v * a.x;
        acc.y += v * a.y;
        acc.z += v * b.x;
        acc.w += v * b.y;
    }

    const float4 b = __ldg(reinterpret_cast<const float4*>(bias) + fo);
    const float4 r = make_float4(acc.x + b.x, acc.y + b.y,
                                 acc.z + b.z, acc.w + b.w);
    __stcs(reinterpret_cast<float4*>(out + (size_t)row * D) + fo, r);
}

// ========================= Launch ==========================================
extern "C" void kernel_launch(void* const* d_in, const int* in_sizes, int n_in,
                              void* d_out, int out_size) {
    const float* x        = (const float*)d_in[0];
    const int*   adj_rows = (const int*)  d_in[1];
    const int*   adj_cols = (const int*)  d_in[2];
    const float* adj_vals = (const float*)d_in[3];
    const float* weight   = (const float*)d_in[4];
    const float* bias     = (const float*)d_in[5];
    float* out = (float*)d_out;

    const int M = in_sizes[0] / D;   // N_NODES
    const int E = in_sizes[1];       // N_EDGES

    // ---- fork: prep chain on side stream, GEMM on main stream ----
    cudaEventRecord(g_fj.fork_ev, 0);
    cudaStreamWaitEvent(g_fj.side, g_fj.fork_ev, 0);

    zero_counts_kernel<<<(M + 255) / 256, 256, 0, g_fj.side>>>(M);
    hist_kernel<<<(E + 255) / 256, 256, 0, g_fj.side>>>(adj_rows, E);
    const int nb = (M + 511) / 512;
    scan1_kernel<<<nb, 512, 0, g_fj.side>>>(M);
    scan2_kernel<<<1, 128, 0, g_fj.side>>>(nb);
    scan3_kernel<<<nb, 512, 0, g_fj.side>>>(M, E);
    place_kernel<<<(E + 255) / 256, 256, 0, g_fj.side>>>(adj_rows, adj_cols,
                                                         adj_vals, E);
    cudaEventRecord(g_fj.join_ev, g_fj.side);

    // GEMM on the main (capture) stream, concurrent with prep
    {
        __half* support;
        cudaGetSymbolAddress((void**)&support, g_support);
        dim3 grid(D / BN, (M + BM - 1) / BM);
        f16_gemm_kernel<<<grid, 256>>>(x, weight, support, M);
    }

    // ---- join: gather needs both GEMM output and CSR ----
    cudaStreamWaitEvent(0, g_fj.join_ev, 0);
    {
        int total_warps = 4 * M;
        int blocks = (total_warps + 7) / 8;
        row_gather_kernel<<<blocks, 256>>>(bias, out, M);
    }
}

// round 13
// speedup vs baseline: 1.1713x; 1.0129x over previous
#include <cuda_runtime.h>
#include <cuda_fp16.h>
#include <cstdint>

// ---------------------------------------------------------------------------
// GraphConvolution: out = SpMM(COO adj, x @ W) + bias
// Round 12: gather -> 2 warps/row with uint4 (LDG.128) support loads (halve
// load-issue count, identical per-element arithmetic). zero_counts launch
// removed (scan3 re-zeroes counts; zero-init at load makes this invariant).
// GEMM: R11 double-buffered (proven). Prep overlap topology: R8 (proven).
// ---------------------------------------------------------------------------

#define D 512
#define MAX_NODES 50000
#define MAX_EDGES 400000

__device__ __half g_support[(size_t)MAX_NODES * D];   // 51.2 MB
__device__ int    g_counts[MAX_NODES];                // zero-init; invariant 0
__device__ int    g_offsets[MAX_NODES + 1];
__device__ int    g_cursors[MAX_NODES];
__device__ int    g_blocksums[256];
__device__ int2   g_perm[MAX_EDGES];

// Host-side fork/join resources, created once at load (not during capture).
struct ForkJoin {
    cudaStream_t side;
    cudaEvent_t  fork_ev, join_ev;
    ForkJoin() {
        cudaStreamCreateWithFlags(&side, cudaStreamNonBlocking);
        cudaEventCreateWithFlags(&fork_ev, cudaEventDisableTiming);
        cudaEventCreateWithFlags(&join_ev, cudaEventDisableTiming);
    }
};
static ForkJoin g_fj;

// ========================= Prep kernels ====================================
__global__ void hist_kernel(const int* __restrict__ rows, int E) {
    int e = blockIdx.x * blockDim.x + threadIdx.x;
    if (e < E) atomicAdd(&g_counts[rows[e]], 1);
}

__global__ __launch_bounds__(512)
void scan1_kernel(int n) {
    __shared__ int ws[16];
    const int tid  = threadIdx.x;
    const int lane = tid & 31;
    const int wid  = tid >> 5;
    const int i = blockIdx.x * 512 + tid;
    const int v = (i < n) ? g_counts[i] : 0;

    int x = v;
    #pragma unroll
    for (int d = 1; d < 32; d <<= 1) {
        int y = __shfl_up_sync(0xffffffffu, x, d);
        if (lane >= d) x += y;
    }
    if (lane == 31) ws[wid] = x;
    __syncthreads();
    if (wid == 0) {
        int w = (lane < 16) ? ws[lane] : 0;
        #pragma unroll
        for (int d = 1; d < 16; d <<= 1) {
            int y = __shfl_up_sync(0xffffffffu, w, d);
            if (lane >= d) w += y;
        }
        if (lane < 16) ws[lane] = w;
    }
    __syncthreads();
    const int excl = (wid ? ws[wid - 1] : 0) + x - v;
    if (i < n) g_offsets[i] = excl;
    if (tid == 511) g_blocksums[blockIdx.x] = ws[15];
}

__global__ __launch_bounds__(128)
void scan2_kernel(int nb) {
    __shared__ int ws[4];
    const int tid  = threadIdx.x;
    const int lane = tid & 31;
    const int wid  = tid >> 5;
    const int v = (tid < nb) ? g_blocksums[tid] : 0;
    int x = v;
    #pragma unroll
    for (int d = 1; d < 32; d <<= 1) {
        int y = __shfl_up_sync(0xffffffffu, x, d);
        if (lane >= d) x += y;
    }
    if (lane == 31) ws[wid] = x;
    __syncthreads();
    if (wid == 0 && lane < 4) {
        int w = ws[lane];
        #pragma unroll
        for (int d = 1; d < 4; d <<= 1) {
            int y = __shfl_up_sync(0x0000000fu, w, d);
            if (lane >= d) w += y;
        }
        ws[lane] = w;
    }
    __syncthreads();
    const int excl = (wid ? ws[wid - 1] : 0) + x - v;
    if (tid < nb) g_blocksums[tid] = excl;
}

// scan3: finalize offsets/cursors AND re-zero counts (restores the invariant
// g_counts == 0 for the next invocation; counts were consumed by scan1).
__global__ __launch_bounds__(512)
void scan3_kernel(int n, int E) {
    const int i = blockIdx.x * 512 + threadIdx.x;
    if (i < n) {
        const int off = g_offsets[i] + g_blocksums[blockIdx.x];
        g_offsets[i] = off;
        g_cursors[i] = off;
        g_counts[i]  = 0;
    }
    if (i == 0) g_offsets[n] = E;
}

__global__ void place_kernel(const int* __restrict__ rows,
                             const int* __restrict__ cols,
                             const float* __restrict__ vals,
                             int E) {
    int e = blockIdx.x * blockDim.x + threadIdx.x;
    if (e >= E) return;
    int pos = atomicAdd(&g_cursors[rows[e]], 1);
    g_perm[pos] = make_int2(cols[e], __float_as_int(vals[e]));
}

// ---------------------------------------------------------------------------
// FP16 tensor-core GEMM (fp32 accum), double-buffered smem, fp16 output.
// CTA tile 128x128x32, 8 warps (4x2), warp tile 32x64, mma.m16n8k16.f16.
// ---------------------------------------------------------------------------
#define BM 128
#define BN 128
#define BK 32
#define KP (BK / 2)
#define SSTRIDE (BM + 8)
#define NTILES (512 / BK)

__device__ __forceinline__ uint32_t pack_h2(float a, float b) {
    __half2 h = __floats2half2_rn(a, b);
    return *reinterpret_cast<uint32_t*>(&h);
}

__global__ __launch_bounds__(256, 2)
void f16_gemm_kernel(const float* __restrict__ A,
                     const float* __restrict__ B,
                     __half* __restrict__ C,
                     int M) {
    constexpr int N = 512, K = 512;

    __shared__ uint32_t As[2][KP][SSTRIDE];
    __shared__ uint32_t Bs[2][KP][SSTRIDE];

    const int tid  = threadIdx.x;
    const int wid  = tid >> 5;
    const int lane = tid & 31;
    const int g    = lane >> 2;
    const int tg   = lane & 3;

    const int wm = (wid >> 1) * 32;
    const int wn = (wid & 1) * 64;

    const int m_base = blockIdx.y * BM;
    const int n_base = blockIdx.x * BN;

    float acc[2][8][4];
    #pragma unroll
    for (int mi = 0; mi < 2; mi++)
        #pragma unroll
        for (int ni = 0; ni < 8; ni++)
            #pragma unroll
            for (int r = 0; r < 4; r++) acc[mi][ni][r] = 0.0f;

    float4 a_stage[4];
    float4 b_stage[2][2];

    auto load_tile = [&](int k0) {
        #pragma unroll
        for (int j = 0; j < 4; j++) {
            const int f   = tid * 4 + j;
            const int row = f >> 3;
            const int kq  = (f & 7) * 4;
            a_stage[j] = make_float4(0.f, 0.f, 0.f, 0.f);
            if (m_base + row < M)
                a_stage[j] = *reinterpret_cast<const float4*>(
                                 A + (size_t)(m_base + row) * K + k0 + kq);
        }
        #pragma unroll
        for (int j = 0; j < 2; j++) {
            const int p  = tid * 2 + j;
            const int kp = p >> 5;
            const int nq = (p & 31) * 4;
            b_stage[j][0] = *reinterpret_cast<const float4*>(
                                B + (size_t)(k0 + 2 * kp) * N + n_base + nq);
            b_stage[j][1] = *reinterpret_cast<const float4*>(
                                B + (size_t)(k0 + 2 * kp + 1) * N + n_base + nq);
        }
    };

    auto commit_tile = [&](int buf) {
        #pragma unroll
        for (int j = 0; j < 4; j++) {
            const int f   = tid * 4 + j;
            const int row = f >> 3;
            const int kq  = (f & 7) * 4;
            const int kp  = kq >> 1;
            As[buf][kp    ][row] = pack_h2(a_stage[j].x, a_stage[j].y);
            As[buf][kp + 1][row] = pack_h2(a_stage[j].z, a_stage[j].w);
        }
        #pragma unroll
        for (int j = 0; j < 2; j++) {
            const int p  = tid * 2 + j;
            const int kp = p >> 5;
            const int nq = (p & 31) * 4;
            uint4 t;
            t.x = pack_h2(b_stage[j][0].x, b_stage[j][1].x);
            t.y = pack_h2(b_stage[j][0].y, b_stage[j][1].y);
            t.z = pack_h2(b_stage[j][0].z, b_stage[j][1].z);
            t.w = pack_h2(b_stage[j][0].w, b_stage[j][1].w);
            *reinterpret_cast<uint4*>(&Bs[buf][kp][nq]) = t;
        }
    };

    load_tile(0);
    commit_tile(0);

    for (int c = 0; c < NTILES; c++) {
        const int buf = c & 1;
        __syncthreads();

        if (c + 1 < NTILES) load_tile((c + 1) * BK);

        #pragma unroll
        for (int ks = 0; ks < KP; ks += 8) {
            uint32_t a[2][4], b[8][2];
            #pragma unroll
            for (int mi = 0; mi < 2; mi++) {
                const int m0 = wm + mi * 16;
                a[mi][0] = As[buf][ks + tg    ][m0 + g    ];
                a[mi][1] = As[buf][ks + tg    ][m0 + g + 8];
                a[mi][2] = As[buf][ks + tg + 4][m0 + g    ];
                a[mi][3] = As[buf][ks + tg + 4][m0 + g + 8];
            }
            #pragma unroll
            for (int ni = 0; ni < 8; ni++) {
                const int n0 = wn + ni * 8;
                b[ni][0] = Bs[buf][ks + tg    ][n0 + g];
                b[ni][1] = Bs[buf][ks + tg + 4][n0 + g];
            }
            #pragma unroll
            for (int mi = 0; mi < 2; mi++)
                #pragma unroll
                for (int ni = 0; ni < 8; ni++) {
                    asm volatile(
                        "mma.sync.aligned.m16n8k16.row.col.f32.f16.f16.f32 "
                        "{%0,%1,%2,%3}, {%4,%5,%6,%7}, {%8,%9}, {%0,%1,%2,%3};"
                        : "+f"(acc[mi][ni][0]), "+f"(acc[mi][ni][1]),
                          "+f"(acc[mi][ni][2]), "+f"(acc[mi][ni][3])
                        : "r"(a[mi][0]), "r"(a[mi][1]), "r"(a[mi][2]), "r"(a[mi][3]),
                          "r"(b[ni][0]), "r"(b[ni][1]));
                }
        }

        if (c + 1 < NTILES) commit_tile(buf ^ 1);
    }

    #pragma unroll
    for (int mi = 0; mi < 2; mi++) {
        const int row0 = m_base + wm + mi * 16 + g;
        const int row1 = row0 + 8;
        #pragma unroll
        for (int ni = 0; ni < 8; ni++) {
            const int col = n_base + wn + ni * 8 + 2 * tg;
            if (row0 < M) {
                __half2 h = __floats2half2_rn(acc[mi][ni][0], acc[mi][ni][1]);
                *reinterpret_cast<__half2*>(C + (size_t)row0 * N + col) = h;
            }
            if (row1 < M) {
                __half2 h = __floats2half2_rn(acc[mi][ni][2], acc[mi][ni][3]);
                *reinterpret_cast<__half2*>(C + (size_t)row1 * N + col) = h;
            }
        }
    }
}

// ---------------------------------------------------------------------------
// Row-gather: 2 warps per output row; each lane owns 8 dims (one uint4 =
// 8 halves per edge -> LDG.128). Per-element edge-order arithmetic identical
// to R8. Unroll-2 for MLP.
// ---------------------------------------------------------------------------
__global__ __launch_bounds__(256)
void row_gather_kernel(const float* __restrict__ bias,
                       float* __restrict__ out,
                       int n_rows) {
    const int gw   = (blockIdx.x * blockDim.x + threadIdx.x) >> 5;
    const int lane = threadIdx.x & 31;
    const int row  = gw >> 1;
    const int part = gw & 1;
    if (row >= n_rows) return;

    const int s = g_offsets[row];
    const int e = g_offsets[row + 1];
    const int fo = part * 32 + lane;   // uint4 index within row, 0..63

    float acc[8];
    #pragma unroll
    for (int q = 0; q < 8; q++) acc[q] = 0.0f;

    int i = s;
    for (; i + 1 < e; i += 2) {
        const int2 cv0 = __ldcs(&g_perm[i]);
        const int2 cv1 = __ldcs(&g_perm[i + 1]);
        const uint4 m0 = __ldg(reinterpret_cast<const uint4*>(
                             g_support + (size_t)cv0.x * D) + fo);
        const uint4 m1 = __ldg(reinterpret_cast<const uint4*>(
                             g_support + (size_t)cv1.x * D) + fo);
        const float v0 = __int_as_float(cv0.y);
        const float v1 = __int_as_float(cv1.y);

        const float2 p00 = __half22float2(*reinterpret_cast<const __half2*>(&m0.x));
        const float2 p01 = __half22float2(*reinterpret_cast<const __half2*>(&m0.y));
        const float2 p02 = __half22float2(*reinterpret_cast<const __half2*>(&m0.z));
        const float2 p03 = __half22float2(*reinterpret_cast<const __half2*>(&m0.w));
        const float2 p10 = __half22float2(*reinterpret_cast<const __half2*>(&m1.x));
        const float2 p11 = __half22float2(*reinterpret_cast<const __half2*>(&m1.y));
        const float2 p12 = __half22float2(*reinterpret_cast<const __half2*>(&m1.z));
        const float2 p13 = __half22float2(*reinterpret_cast<const __half2*>(&m1.w));

        acc[0] += v0 * p00.x + v1 * p10.x;
        acc[1] += v0 * p00.y + v1 * p10.y;
        acc[2] += v0 * p01.x + v1 * p11.x;
        acc[3] += v0 * p01.y + v1 * p11.y;
        acc[4] += v0 * p02.x + v1 * p12.x;
        acc[5] += v0 * p02.y + v1 * p12.y;
        acc[6] += v0 * p03.x + v1 * p13.x;
        acc[7] += v0 * p03.y + v1 * p13.y;
    }
    for (; i < e; i++) {
        const int2 cv = __ldcs(&g_perm[i]);
        const float v = __int_as_float(cv.y);
        const uint4 m = __ldg(reinterpret_cast<const uint4*>(
                            g_support + (size_t)cv.x * D) + fo);
        const float2 p0 = __half22float2(*reinterpret_cast<const __half2*>(&m.x));
        const float2 p1 = __half22float2(*reinterpret_cast<const __half2*>(&m.y));
        const float2 p2 = __half22float2(*reinterpret_cast<const __half2*>(&m.z));
        const float2 p3 = __half22float2(*reinterpret_cast<const __half2*>(&m.w));
        acc[0] += v * p0.x;
        acc[1] += v * p0.y;
        acc[2] += v * p1.x;
        acc[3] += v * p1.y;
        acc[4] += v * p2.x;
        acc[5] += v * p2.y;
        acc[6] += v * p3.x;
        acc[7] += v * p3.y;
    }

    // each lane covers 8 consecutive floats: two float4 stores
    const float4 b0 = __ldg(reinterpret_cast<const float4*>(bias) + 2 * fo);
    const float4 b1 = __ldg(reinterpret_cast<const float4*>(bias) + 2 * fo + 1);
    float4* op = reinterpret_cast<float4*>(out + (size_t)row * D) + 2 * fo;
    __stcs(op,     make_float4(acc[0] + b0.x, acc[1] + b0.y,
                               acc[2] + b0.z, acc[3] + b0.w));
    __stcs(op + 1, make_float4(acc[4] + b1.x, acc[5] + b1.y,
                               acc[6] + b1.z, acc[7] + b1.w));
}

// ========================= Launch ==========================================
extern "C" void kernel_launch(void* const* d_in, const int* in_sizes, int n_in,
                              void* d_out, int out_size) {
    const float* x        = (const float*)d_in[0];
    const int*   adj_rows = (const int*)  d_in[1];
    const int*   adj_cols = (const int*)  d_in[2];
    const float* adj_vals = (const float*)d_in[3];
    const float* weight   = (const float*)d_in[4];
    const float* bias     = (const float*)d_in[5];
    float* out = (float*)d_out;

    const int M = in_sizes[0] / D;   // N_NODES
    const int E = in_sizes[1];       // N_EDGES

    // ---- fork: prep chain on side stream, GEMM on main stream ----
    cudaEventRecord(g_fj.fork_ev, 0);
    cudaStreamWaitEvent(g_fj.side, g_fj.fork_ev, 0);

    // counts is 0 here (zero-init at load; scan3 restores it every call)
    hist_kernel<<<(E + 255) / 256, 256, 0, g_fj.side>>>(adj_rows, E);
    const int nb = (M + 511) / 512;
    scan1_kernel<<<nb, 512, 0, g_fj.side>>>(M);
    scan2_kernel<<<1, 128, 0, g_fj.side>>>(nb);
    scan3_kernel<<<nb, 512, 0, g_fj.side>>>(M, E);
    place_kernel<<<(E + 255) / 256, 256, 0, g_fj.side>>>(adj_rows, adj_cols,
                                                         adj_vals, E);
    cudaEventRecord(g_fj.join_ev, g_fj.side);

    // GEMM on the main (capture) stream, concurrent with prep
    {
        __half* support;
        cudaGetSymbolAddress((void**)&support, g_support);
        dim3 grid(D / BN, (M + BM - 1) / BM);
        f16_gemm_kernel<<<grid, 256>>>(x, weight, support, M);
    }

    // ---- join: gather needs both GEMM output and CSR ----
    cudaStreamWaitEvent(0, g_fj.join_ev, 0);
    {
        int total_warps = 2 * M;
        int blocks = (total_warps + 7) / 8;
        row_gather_kernel<<<blocks, 256>>>(bias, out, M);
    }
}

// round 14
// speedup vs baseline: 1.2691x; 1.0835x over previous
#include <cuda_runtime.h>
#include <cuda_fp16.h>
#include <cstdint>

// ---------------------------------------------------------------------------
// GraphConvolution: out = SpMM(COO adj, x @ W) + bias
// Round 13: GEMM CTA tile widened to 128x256 (BN 128->256, 512 threads,
// 1 CTA/SM) halving redundant A reads (409 MB -> 205 MB DRAM traffic).
// Gather/prep/topology identical to R12 (proven 238.8).
// ---------------------------------------------------------------------------

#define D 512
#define MAX_NODES 50000
#define MAX_EDGES 400000

__device__ __half g_support[(size_t)MAX_NODES * D];   // 51.2 MB
__device__ int    g_counts[MAX_NODES];                // zero-init; invariant 0
__device__ int    g_offsets[MAX_NODES + 1];
__device__ int    g_cursors[MAX_NODES];
__device__ int    g_blocksums[256];
__device__ int2   g_perm[MAX_EDGES];

struct ForkJoin {
    cudaStream_t side;
    cudaEvent_t  fork_ev, join_ev;
    ForkJoin() {
        cudaStreamCreateWithFlags(&side, cudaStreamNonBlocking);
        cudaEventCreateWithFlags(&fork_ev, cudaEventDisableTiming);
        cudaEventCreateWithFlags(&join_ev, cudaEventDisableTiming);
    }
};
static ForkJoin g_fj;

// ========================= Prep kernels ====================================
__global__ void hist_kernel(const int* __restrict__ rows, int E) {
    int e = blockIdx.x * blockDim.x + threadIdx.x;
    if (e < E) atomicAdd(&g_counts[rows[e]], 1);
}

__global__ __launch_bounds__(512)
void scan1_kernel(int n) {
    __shared__ int ws[16];
    const int tid  = threadIdx.x;
    const int lane = tid & 31;
    const int wid  = tid >> 5;
    const int i = blockIdx.x * 512 + tid;
    const int v = (i < n) ? g_counts[i] : 0;

    int x = v;
    #pragma unroll
    for (int d = 1; d < 32; d <<= 1) {
        int y = __shfl_up_sync(0xffffffffu, x, d);
        if (lane >= d) x += y;
    }
    if (lane == 31) ws[wid] = x;
    __syncthreads();
    if (wid == 0) {
        int w = (lane < 16) ? ws[lane] : 0;
        #pragma unroll
        for (int d = 1; d < 16; d <<= 1) {
            int y = __shfl_up_sync(0xffffffffu, w, d);
            if (lane >= d) w += y;
        }
        if (lane < 16) ws[lane] = w;
    }
    __syncthreads();
    const int excl = (wid ? ws[wid - 1] : 0) + x - v;
    if (i < n) g_offsets[i] = excl;
    if (tid == 511) g_blocksums[blockIdx.x] = ws[15];
}

__global__ __launch_bounds__(128)
void scan2_kernel(int nb) {
    __shared__ int ws[4];
    const int tid  = threadIdx.x;
    const int lane = tid & 31;
    const int wid  = tid >> 5;
    const int v = (tid < nb) ? g_blocksums[tid] : 0;
    int x = v;
    #pragma unroll
    for (int d = 1; d < 32; d <<= 1) {
        int y = __shfl_up_sync(0xffffffffu, x, d);
        if (lane >= d) x += y;
    }
    if (lane == 31) ws[wid] = x;
    __syncthreads();
    if (wid == 0 && lane < 4) {
        int w = ws[lane];
        #pragma unroll
        for (int d = 1; d < 4; d <<= 1) {
            int y = __shfl_up_sync(0x0000000fu, w, d);
            if (lane >= d) w += y;
        }
        ws[lane] = w;
    }
    __syncthreads();
    const int excl = (wid ? ws[wid - 1] : 0) + x - v;
    if (tid < nb) g_blocksums[tid] = excl;
}

__global__ __launch_bounds__(512)
void scan3_kernel(int n, int E) {
    const int i = blockIdx.x * 512 + threadIdx.x;
    if (i < n) {
        const int off = g_offsets[i] + g_blocksums[blockIdx.x];
        g_offsets[i] = off;
        g_cursors[i] = off;
        g_counts[i]  = 0;   // restore invariant for next invocation
    }
    if (i == 0) g_offsets[n] = E;
}

__global__ void place_kernel(const int* __restrict__ rows,
                             const int* __restrict__ cols,
                             const float* __restrict__ vals,
                             int E) {
    int e = blockIdx.x * blockDim.x + threadIdx.x;
    if (e >= E) return;
    int pos = atomicAdd(&g_cursors[rows[e]], 1);
    g_perm[pos] = make_int2(cols[e], __float_as_int(vals[e]));
}

// ---------------------------------------------------------------------------
// FP16 tensor-core GEMM (fp32 accum), double-buffered, CTA tile 128x256x32.
// 512 threads = 16 warps in a 4(m) x 4(n) grid; warp tile 32x64.
// A DRAM traffic halves vs BN=128 (grid.x = 2).
// ---------------------------------------------------------------------------
#define BM 128
#define BN 256
#define BK 32
#define KP (BK / 2)
#define ASTRIDE (BM + 8)    // 136; %32==8 -> conflict-free
#define BSTRIDE (BN + 8)    // 264; %32==8 -> conflict-free
#define NTILES (512 / BK)   // 16

__device__ __forceinline__ uint32_t pack_h2(float a, float b) {
    __half2 h = __floats2half2_rn(a, b);
    return *reinterpret_cast<uint32_t*>(&h);
}

__global__ __launch_bounds__(512, 1)
void f16_gemm_kernel(const float* __restrict__ A,
                     const float* __restrict__ B,
                     __half* __restrict__ C,
                     int M) {
    constexpr int N = 512, K = 512;

    __shared__ uint32_t As[2][KP][ASTRIDE];   // 17.4 KB
    __shared__ uint32_t Bs[2][KP][BSTRIDE];   // 33.8 KB

    const int tid  = threadIdx.x;
    const int wid  = tid >> 5;
    const int lane = tid & 31;
    const int g    = lane >> 2;
    const int tg   = lane & 3;

    const int wm = (wid >> 2) * 32;    // 0,32,64,96
    const int wn = (wid & 3) * 64;     // 0,64,128,192

    const int m_base = blockIdx.y * BM;
    const int n_base = blockIdx.x * BN;

    float acc[2][8][4];
    #pragma unroll
    for (int mi = 0; mi < 2; mi++)
        #pragma unroll
        for (int ni = 0; ni < 8; ni++)
            #pragma unroll
            for (int r = 0; r < 4; r++) acc[mi][ni][r] = 0.0f;

    // A tile: 128x32 fp32 = 1024 float4; 2/thread.
    // B tile: 32x256 fp32, loaded as k-row pairs; p = tid*2+j (0..1023),
    //         kp = p>>6 (0..15), nq = (p&63)*4 (0..252); 2 float4 per p.
    float4 a_stage[2];
    float4 b_stage[2][2];

    auto load_tile = [&](int k0) {
        #pragma unroll
        for (int j = 0; j < 2; j++) {
            const int f   = tid * 2 + j;
            const int row = f >> 3;
            const int kq  = (f & 7) * 4;
            a_stage[j] = make_float4(0.f, 0.f, 0.f, 0.f);
            if (m_base + row < M)
                a_stage[j] = *reinterpret_cast<const float4*>(
                                 A + (size_t)(m_base + row) * K + k0 + kq);
        }
        #pragma unroll
        for (int j = 0; j < 2; j++) {
            const int p  = tid * 2 + j;
            const int kp = p >> 6;
            const int nq = (p & 63) * 4;
            b_stage[j][0] = *reinterpret_cast<const float4*>(
                                B + (size_t)(k0 + 2 * kp) * N + n_base + nq);
            b_stage[j][1] = *reinterpret_cast<const float4*>(
                                B + (size_t)(k0 + 2 * kp + 1) * N + n_base + nq);
        }
    };

    auto commit_tile = [&](int buf) {
        #pragma unroll
        for (int j = 0; j < 2; j++) {
            const int f   = tid * 2 + j;
            const int row = f >> 3;
            const int kq  = (f & 7) * 4;
            const int kp  = kq >> 1;
            As[buf][kp    ][row] = pack_h2(a_stage[j].x, a_stage[j].y);
            As[buf][kp + 1][row] = pack_h2(a_stage[j].z, a_stage[j].w);
        }
        #pragma unroll
        for (int j = 0; j < 2; j++) {
            const int p  = tid * 2 + j;
            const int kp = p >> 6;
            const int nq = (p & 63) * 4;
            uint4 t;
            t.x = pack_h2(b_stage[j][0].x, b_stage[j][1].x);
            t.y = pack_h2(b_stage[j][0].y, b_stage[j][1].y);
            t.z = pack_h2(b_stage[j][0].z, b_stage[j][1].z);
            t.w = pack_h2(b_stage[j][0].w, b_stage[j][1].w);
            *reinterpret_cast<uint4*>(&Bs[buf][kp][nq]) = t;
        }
    };

    load_tile(0);
    commit_tile(0);

    for (int c = 0; c < NTILES; c++) {
        const int buf = c & 1;
        __syncthreads();

        if (c + 1 < NTILES) load_tile((c + 1) * BK);

        #pragma unroll
        for (int ks = 0; ks < KP; ks += 8) {
            uint32_t a[2][4], b[8][2];
            #pragma unroll
            for (int mi = 0; mi < 2; mi++) {
                const int m0 = wm + mi * 16;
                a[mi][0] = As[buf][ks + tg    ][m0 + g    ];
                a[mi][1] = As[buf][ks + tg    ][m0 + g + 8];
                a[mi][2] = As[buf][ks + tg + 4][m0 + g    ];
                a[mi][3] = As[buf][ks + tg + 4][m0 + g + 8];
            }
            #pragma unroll
            for (int ni = 0; ni < 8; ni++) {
                const int n0 = wn + ni * 8;
                b[ni][0] = Bs[buf][ks + tg    ][n0 + g];
                b[ni][1] = Bs[buf][ks + tg + 4][n0 + g];
            }
            #pragma unroll
            for (int mi = 0; mi < 2; mi++)
                #pragma unroll
                for (int ni = 0; ni < 8; ni++) {
                    asm volatile(
                        "mma.sync.aligned.m16n8k16.row.col.f32.f16.f16.f32 "
                        "{%0,%1,%2,%3}, {%4,%5,%6,%7}, {%8,%9}, {%0,%1,%2,%3};"
                        : "+f"(acc[mi][ni][0]), "+f"(acc[mi][ni][1]),
                          "+f"(acc[mi][ni][2]), "+f"(acc[mi][ni][3])
                        : "r"(a[mi][0]), "r"(a[mi][1]), "r"(a[mi][2]), "r"(a[mi][3]),
                          "r"(b[ni][0]), "r"(b[ni][1]));
                }
        }

        if (c + 1 < NTILES) commit_tile(buf ^ 1);
    }

    #pragma unroll
    for (int mi = 0; mi < 2; mi++) {
        const int row0 = m_base + wm + mi * 16 + g;
        const int row1 = row0 + 8;
        #pragma unroll
        for (int ni = 0; ni < 8; ni++) {
            const int col = n_base + wn + ni * 8 + 2 * tg;
            if (row0 < M) {
                __half2 h = __floats2half2_rn(acc[mi][ni][0], acc[mi][ni][1]);
                *reinterpret_cast<__half2*>(C + (size_t)row0 * N + col) = h;
            }
            if (row1 < M) {
                __half2 h = __floats2half2_rn(acc[mi][ni][2], acc[mi][ni][3]);
                *reinterpret_cast<__half2*>(C + (size_t)row1 * N + col) = h;
            }
        }
    }
}

// ---------------------------------------------------------------------------
// Row-gather: 2 warps/row, uint4 (LDG.128) support loads. (R12 exact)
// ---------------------------------------------------------------------------
__global__ __launch_bounds__(256)
void row_gather_kernel(const float* __restrict__ bias,
                       float* __restrict__ out,
                       int n_rows) {
    const int gw   = (blockIdx.x * blockDim.x + threadIdx.x) >> 5;
    const int lane = threadIdx.x & 31;
    const int row  = gw >> 1;
    const int part = gw & 1;
    if (row >= n_rows) return;

    const int s = g_offsets[row];
    const int e = g_offsets[row + 1];
    const int fo = part * 32 + lane;

    float acc[8];
    #pragma unroll
    for (int q = 0; q < 8; q++) acc[q] = 0.0f;

    int i = s;
    for (; i + 1 < e; i += 2) {
        const int2 cv0 = __ldcs(&g_perm[i]);
        const int2 cv1 = __ldcs(&g_perm[i + 1]);
        const uint4 m0 = __ldg(reinterpret_cast<const uint4*>(
                             g_support + (size_t)cv0.x * D) + fo);
        const uint4 m1 = __ldg(reinterpret_cast<const uint4*>(
                             g_support + (size_t)cv1.x * D) + fo);
        const float v0 = __int_as_float(cv0.y);
        const float v1 = __int_as_float(cv1.y);

        const float2 p00 = __half22float2(*reinterpret_cast<const __half2*>(&m0.x));
        const float2 p01 = __half22float2(*reinterpret_cast<const __half2*>(&m0.y));
        const float2 p02 = __half22float2(*reinterpret_cast<const __half2*>(&m0.z));
        const float2 p03 = __half22float2(*reinterpret_cast<const __half2*>(&m0.w));
        const float2 p10 = __half22float2(*reinterpret_cast<const __half2*>(&m1.x));
        const float2 p11 = __half22float2(*reinterpret_cast<const __half2*>(&m1.y));
        const float2 p12 = __half22float2(*reinterpret_cast<const __half2*>(&m1.z));
        const float2 p13 = __half22float2(*reinterpret_cast<const __half2*>(&m1.w));

        acc[0] += v0 * p00.x + v1 * p10.x;
        acc[1] += v0 * p00.y + v1 * p10.y;
        acc[2] += v0 * p01.x + v1 * p11.x;
        acc[3] += v0 * p01.y + v1 * p11.y;
        acc[4] += v0 * p02.x + v1 * p12.x;
        acc[5] += v0 * p02.y + v1 * p12.y;
        acc[6] += v0 * p03.x + v1 * p13.x;
        acc[7] += v0 * p03.y + v1 * p13.y;
    }
    for (; i < e; i++) {
        const int2 cv = __ldcs(&g_perm[i]);
        const float v = __int_as_float(cv.y);
        const uint4 m = __ldg(reinterpret_cast<const uint4*>(
                            g_support + (size_t)cv.x * D) + fo);
        const float2 p0 = __half22float2(*reinterpret_cast<const __half2*>(&m.x));
        const float2 p1 = __half22float2(*reinterpret_cast<const __half2*>(&m.y));
        const float2 p2 = __half22float2(*reinterpret_cast<const __half2*>(&m.z));
        const float2 p3 = __half22float2(*reinterpret_cast<const __half2*>(&m.w));
        acc[0] += v * p0.x;
        acc[1] += v * p0.y;
        acc[2] += v * p1.x;
        acc[3] += v * p1.y;
        acc[4] += v * p2.x;
        acc[5] += v * p2.y;
        acc[6] += v * p3.x;
        acc[7] += v * p3.y;
    }

    const float4 b0 = __ldg(reinterpret_cast<const float4*>(bias) + 2 * fo);
    const float4 b1 = __ldg(reinterpret_cast<const float4*>(bias) + 2 * fo + 1);
    float4* op = reinterpret_cast<float4*>(out + (size_t)row * D) + 2 * fo;
    __stcs(op,     make_float4(acc[0] + b0.x, acc[1] + b0.y,
                               acc[2] + b0.z, acc[3] + b0.w));
    __stcs(op + 1, make_float4(acc[4] + b1.x, acc[5] + b1.y,
                               acc[6] + b1.z, acc[7] + b1.w));
}

// ========================= Launch ==========================================
extern "C" void kernel_launch(void* const* d_in, const int* in_sizes, int n_in,
                              void* d_out, int out_size) {
    const float* x        = (const float*)d_in[0];
    const int*   adj_rows = (const int*)  d_in[1];
    const int*   adj_cols = (const int*)  d_in[2];
    const float* adj_vals = (const float*)d_in[3];
    const float* weight   = (const float*)d_in[4];
    const float* bias     = (const float*)d_in[5];
    float* out = (float*)d_out;

    const int M = in_sizes[0] / D;   // N_NODES
    const int E = in_sizes[1];       // N_EDGES

    // ---- fork: prep chain on side stream, GEMM on main stream ----
    cudaEventRecord(g_fj.fork_ev, 0);
    cudaStreamWaitEvent(g_fj.side, g_fj.fork_ev, 0);

    hist_kernel<<<(E + 255) / 256, 256, 0, g_fj.side>>>(adj_rows, E);
    const int nb = (M + 511) / 512;
    scan1_kernel<<<nb, 512, 0, g_fj.side>>>(M);
    scan2_kernel<<<1, 128, 0, g_fj.side>>>(nb);
    scan3_kernel<<<nb, 512, 0, g_fj.side>>>(M, E);
    place_kernel<<<(E + 255) / 256, 256, 0, g_fj.side>>>(adj_rows, adj_cols,
                                                         adj_vals, E);
    cudaEventRecord(g_fj.join_ev, g_fj.side);

    // GEMM on the main (capture) stream, concurrent with prep
    {
        __half* support;
        cudaGetSymbolAddress((void**)&support, g_support);
        dim3 grid(512 / BN, (M + BM - 1) / BM);   // (2, 391)
        f16_gemm_kernel<<<grid, 512>>>(x, weight, support, M);
    }

    // ---- join: gather needs both GEMM output and CSR ----
    cudaStreamWaitEvent(0, g_fj.join_ev, 0);
    {
        int total_warps = 2 * M;
        int blocks = (total_warps + 7) / 8;
        row_gather_kernel<<<blocks, 256>>>(bias, out, M);
    }
}